// round 15
// baseline (speedup 1.0000x reference)
#include <cuda_runtime.h>
#include <cuda_bf16.h>
#include <cuda_fp16.h>
#include <cstdint>

// ---------------- problem constants ----------------
#define D_MODEL   1024
#define S_LEN     2048
#define BATCH     4
#define N_HEADS   16
#define HEAD_DIM  64
#define BHX       (BATCH * N_HEADS)                          // 64
#define M_TOT     (BATCH * S_LEN)                            // 8192
#define ATTN_OUT_ELEMS  (BATCH * S_LEN * D_MODEL)            // 8388608
#define BIAS_OUT_ELEMS  (N_HEADS * S_LEN * S_LEN)            // 67108864

// ---------------- device scratch ----------------
__device__ __nv_bfloat16 g_Hh[(size_t)M_TOT * D_MODEL];
__device__ __nv_bfloat16 g_Hl[(size_t)M_TOT * D_MODEL];
__device__ __nv_bfloat16 g_Wh[4ull * D_MODEL * D_MODEL];
__device__ __nv_bfloat16 g_Wl[4ull * D_MODEL * D_MODEL];
__device__ __nv_bfloat16 g_Qh[(size_t)BHX * S_LEN * HEAD_DIM];
__device__ __nv_bfloat16 g_Ql[(size_t)BHX * S_LEN * HEAD_DIM];
__device__ __nv_bfloat16 g_Kh[(size_t)BHX * S_LEN * HEAD_DIM];
__device__ __nv_bfloat16 g_Kl[(size_t)BHX * S_LEN * HEAD_DIM];
__device__ __half        g_Vf[(size_t)BHX * S_LEN * HEAD_DIM];   // V single fp16
__device__ __nv_bfloat16 g_Oh[(size_t)M_TOT * D_MODEL];
__device__ __nv_bfloat16 g_Ol[(size_t)M_TOT * D_MODEL];
__device__ int g_lut[4096];

// ---------------- helpers ----------------
__device__ __forceinline__ uint32_t smem_u32(const void* p) {
    uint32_t a;
    asm("{ .reg .u64 t; cvta.to.shared.u64 t, %1; cvt.u32.u64 %0, t; }" : "=r"(a) : "l"(p));
    return a;
}
// row of 128B (8 x 16B chunks); XOR-swizzle chunk by row&7
__device__ __forceinline__ uint32_t sw_off(int row, int c) {
    return (uint32_t)(row * 128 + ((c ^ (row & 7)) << 4));
}
#define CP16(dst, src) asm volatile("cp.async.cg.shared.global [%0], [%1], 16;" :: "r"(dst), "l"(src))
#define CP_COMMIT()    asm volatile("cp.async.commit_group;" ::: "memory")
#define CP_WAIT(n)     asm volatile("cp.async.wait_group %0;" :: "n"(n) : "memory")

__device__ __forceinline__ void ldsm4(uint32_t r[4], uint32_t a) {
    asm volatile("ldmatrix.sync.aligned.m8n8.x4.shared.b16 {%0,%1,%2,%3}, [%4];"
                 : "=r"(r[0]), "=r"(r[1]), "=r"(r[2]), "=r"(r[3]) : "r"(a));
}
__device__ __forceinline__ void ldsm4t(uint32_t r[4], uint32_t a) {
    asm volatile("ldmatrix.sync.aligned.m8n8.x4.trans.shared.b16 {%0,%1,%2,%3}, [%4];"
                 : "=r"(r[0]), "=r"(r[1]), "=r"(r[2]), "=r"(r[3]) : "r"(a));
}
__device__ __forceinline__ void mma16816(float* c, const uint32_t* a, const uint32_t* b) {
    asm volatile("mma.sync.aligned.m16n8k16.row.col.f32.bf16.bf16.f32 "
                 "{%0,%1,%2,%3}, {%4,%5,%6,%7}, {%8,%9}, {%0,%1,%2,%3};"
                 : "+f"(c[0]), "+f"(c[1]), "+f"(c[2]), "+f"(c[3])
                 : "r"(a[0]), "r"(a[1]), "r"(a[2]), "r"(a[3]), "r"(b[0]), "r"(b[1]));
}
__device__ __forceinline__ void mma16816h(float* c, const uint32_t* a, const uint32_t* b) {
    asm volatile("mma.sync.aligned.m16n8k16.row.col.f32.f16.f16.f32 "
                 "{%0,%1,%2,%3}, {%4,%5,%6,%7}, {%8,%9}, {%0,%1,%2,%3};"
                 : "+f"(c[0]), "+f"(c[1]), "+f"(c[2]), "+f"(c[3])
                 : "r"(a[0]), "r"(a[1]), "r"(a[2]), "r"(a[3]), "r"(b[0]), "r"(b[1]));
}
__device__ __forceinline__ uint32_t packbf(float a, float b) {
    __nv_bfloat162 t = __floats2bfloat162_rn(a, b);
    return *(uint32_t*)&t;
}
__device__ __forceinline__ uint32_t packhf(float a, float b) {
    __half2 t = __floats2half2_rn(a, b);
    return *(uint32_t*)&t;
}
__device__ __forceinline__ void hilo(float x, float& h, float& l) {
    __nv_bfloat16 hb = __float2bfloat16(x);
    h = __bfloat162float(hb);
    l = x - h;
}

// ---------------- bucket LUT (exact integer math) ----------------
__global__ void lut_kernel() {
    int i = blockIdx.x * blockDim.x + threadIdx.x;
    if (i >= 4096) return;
    int d  = i - 2048;
    int rb = (d > 0) ? 16 : 0;
    int rp = (d < 0) ? -d : d;
    int b;
    if (rp < 8) b = rp;
    else {
        int n = (31 - __clz(rp * rp)) - 6;
        b = 8 + n;
        if (b > 15) b = 15;
    }
    g_lut[i] = rb + b;
}

// ---------------- fp32 -> bf16 hi/lo, 8 elements/thread ----------------
__device__ __forceinline__ void cvt_group8(const float4* s4, uint4* h4, uint4* l4, size_t g) {
    float4 a = s4[2 * g], b = s4[2 * g + 1];
    float x[8] = {a.x, a.y, a.z, a.w, b.x, b.y, b.z, b.w};
    float h[8], l[8];
#pragma unroll
    for (int t = 0; t < 8; t++) hilo(x[t], h[t], l[t]);
    h4[g] = make_uint4(packbf(h[0], h[1]), packbf(h[2], h[3]), packbf(h[4], h[5]), packbf(h[6], h[7]));
    l4[g] = make_uint4(packbf(l[0], l[1]), packbf(l[2], l[3]), packbf(l[4], l[5]), packbf(l[6], l[7]));
}

__global__ void cvtH_kernel(const float* __restrict__ src, int n8) {
    const float4* s4 = (const float4*)src;
    uint4* h4 = (uint4*)g_Hh;
    uint4* l4 = (uint4*)g_Hl;
    for (int g = blockIdx.x * blockDim.x + threadIdx.x; g < n8; g += gridDim.x * blockDim.x)
        cvt_group8(s4, h4, l4, g);
}

__global__ void cvtW_kernel(const float* __restrict__ w0, const float* __restrict__ w1,
                            const float* __restrict__ w2, const float* __restrict__ w3) {
    int z = blockIdx.y;
    const float* src = (z == 0) ? w0 : (z == 1) ? w1 : (z == 2) ? w2 : w3;
    const float4* s4 = (const float4*)src;
    uint4* h4 = (uint4*)(g_Wh + (size_t)z * D_MODEL * D_MODEL);
    uint4* l4 = (uint4*)(g_Wl + (size_t)z * D_MODEL * D_MODEL);
    const int n8 = D_MODEL * D_MODEL / 8;
    for (int g = blockIdx.x * blockDim.x + threadIdx.x; g < n8; g += gridDim.x * blockDim.x)
        cvt_group8(s4, h4, l4, g);
}

// ---------------- warp-MMA GEMM: C[8192,1024] = A * B^T ----------------
// tile 128x128, K-chunk 32, 3-stage cp.async pipeline, 2 CTAs/SM.
// Stage (32 KB): A block 16KB (row r 128B = [Ah 64B | Al 64B]), B block 16KB.
#define G_STAGE 32768
#define G_SMEM  (3 * G_STAGE)

__global__ __launch_bounds__(256, 2) void mm_gemm(int op, float* __restrict__ out) {
    extern __shared__ char sm[];
    uint32_t sb = smem_u32(sm);
    const int tid = threadIdx.x, lane = tid & 31, wid = tid >> 5;
    const int wm = wid & 1, wn = wid >> 1;       // 2 x 4 warps, warp tile 64m x 32n
    int mode = (op == 3) ? 3 : (int)blockIdx.z;
    const __nv_bfloat16* Ah = (op == 3) ? g_Oh : g_Hh;
    const __nv_bfloat16* Al = (op == 3) ? g_Ol : g_Hl;
    const __nv_bfloat16* Bh = g_Wh + (size_t)mode * D_MODEL * D_MODEL;
    const __nv_bfloat16* Bl = g_Wl + (size_t)mode * D_MODEL * D_MODEL;
    const int m0 = blockIdx.y * 128, n0 = blockIdx.x * 128;

    float acc[4][4][4];
#pragma unroll
    for (int i = 0; i < 4; i++)
#pragma unroll
        for (int j = 0; j < 4; j++)
#pragma unroll
            for (int k = 0; k < 4; k++) acc[i][j][k] = 0.f;

    auto issue = [&](int kc, int slot) {
        uint32_t base = sb + slot * G_STAGE;
#pragma unroll
        for (int j = 0; j < 8; j++) {
            int idx = j * 256 + tid;             // 0..2047
            int mt  = idx >> 10;                 // 0 = A, 1 = B
            int i2  = idx & 1023;
            int r = i2 >> 3, c = i2 & 7;
            const __nv_bfloat16* G;
            if (mt == 0) G = ((c < 4) ? Ah : Al) + (size_t)(m0 + r) * 1024;
            else         G = ((c < 4) ? Bh : Bl) + (size_t)(n0 + r) * 1024;
            CP16(base + mt * 16384 + sw_off(r, c), G + kc * 32 + (c & 3) * 8);
        }
        CP_COMMIT();
    };

    issue(0, 0);
    issue(1, 1);

    const int mat = lane >> 3;
    const int rh = (mat & 1) * 8 + (lane & 7);

    for (int kc = 0; kc < 32; kc++) {
        if (kc == 31) { CP_WAIT(0); } else { CP_WAIT(1); }
        __syncthreads();
        if (kc + 2 < 32) issue(kc + 2, (kc + 2) % 3);
        uint32_t base = sb + (kc % 3) * G_STAGE;
#pragma unroll
        for (int ks = 0; ks < 2; ks++) {
            int cc = (mat >> 1) + ks * 2;        // hi chunks 0..3; lo = +4
            uint32_t ah[4][4], al[4][4];
#pragma unroll
            for (int mf = 0; mf < 4; mf++) {
                int row = wm * 64 + mf * 16 + rh;
                ldsm4(ah[mf], base + sw_off(row, cc));
                ldsm4(al[mf], base + sw_off(row, cc + 4));
            }
            uint32_t bh[4][2], bl[4][2];
#pragma unroll
            for (int p = 0; p < 2; p++) {
                int row = wn * 32 + p * 16 + rh;
                uint32_t t[4];
                ldsm4(t, base + 16384 + sw_off(row, cc));
                bh[2*p][0] = t[0]; bh[2*p][1] = t[2];
                bh[2*p+1][0] = t[1]; bh[2*p+1][1] = t[3];
                ldsm4(t, base + 16384 + sw_off(row, cc + 4));
                bl[2*p][0] = t[0]; bl[2*p][1] = t[2];
                bl[2*p+1][0] = t[1]; bl[2*p+1][1] = t[3];
            }
#pragma unroll
            for (int mf = 0; mf < 4; mf++)
#pragma unroll
                for (int nf = 0; nf < 4; nf++) {
                    mma16816(acc[mf][nf], ah[mf], bh[nf]);
                    mma16816(acc[mf][nf], ah[mf], bl[nf]);
                    mma16816(acc[mf][nf], al[mf], bh[nf]);
                }
        }
    }

    // epilogue
#pragma unroll
    for (int mf = 0; mf < 4; mf++)
#pragma unroll
        for (int nf = 0; nf < 4; nf++) {
            int r0 = m0 + wm * 64 + mf * 16 + (lane >> 2);
            int col = n0 + wn * 32 + nf * 8 + (lane & 3) * 2;
            float* c = acc[mf][nf];
            if (mode == 3) {
                *(float2*)(out + (size_t)r0 * 1024 + col)       = make_float2(c[0], c[1]);
                *(float2*)(out + (size_t)(r0 + 8) * 1024 + col) = make_float2(c[2], c[3]);
            } else {
                int h = col >> 6, dh = col & 63;
#pragma unroll
                for (int rr = 0; rr < 2; rr++) {
                    int gi = r0 + rr * 8;
                    int b = gi >> 11, s = gi & 2047;
                    size_t o = ((size_t)(b * 16 + h) * 2048 + s) * 64 + dh;
                    if (mode == 2) {
                        *(uint32_t*)(g_Vf + o) = packhf(c[rr * 2], c[rr * 2 + 1]);
                    } else {
                        __nv_bfloat16* Dh = (mode == 0) ? g_Qh : g_Kh;
                        __nv_bfloat16* Dl = (mode == 0) ? g_Ql : g_Kl;
                        float h0, l0v, h1, l1v;
                        hilo(c[rr * 2], h0, l0v);
                        hilo(c[rr * 2 + 1], h1, l1v);
                        *(uint32_t*)(Dh + o) = packbf(h0, h1);
                        *(uint32_t*)(Dl + o) = packbf(l0v, l1v);
                    }
                }
            }
        }
}

// ---------------- warp-MMA flash attention ----------------
// CTA: 64 q rows x bh. 128 threads = 4 warps. 2 CTAs/SM, 3-stage KV pipeline.
// smem: QH 0 (8K), QL 8192 (8K); stages at 16384 (stride 24576): KH+0 KL+8192 VF+16384;
//       bias f32 @90112 (16K). total 106496.
#define A_QH    0
#define A_QL    8192
#define A_STG   16384
#define A_SSTR  24576
#define A_KH    0
#define A_KL    8192
#define A_VF    16384
#define A_BIAS  90112
#define A_SMEM  106496

__global__ __launch_bounds__(128, 2) void mm_attn(const float* __restrict__ emb) {
    extern __shared__ char sm[];
    uint32_t sb = smem_u32(sm);
    float* biasS = (float*)(sm + A_BIAS);
    const int tid = threadIdx.x, lane = tid & 31, w = tid >> 5;
    const int bh = blockIdx.y, h = bh & 15, b = bh >> 4;
    const int q0 = blockIdx.x * 64;

    auto issueKV = [&](int kt, int slot) {
        uint32_t base = sb + A_STG + slot * A_SSTR;
#pragma unroll
        for (int j = 0; j < 12; j++) {
            int idx = j * 128 + tid;             // 0..1535
            int mt = idx >> 9;                   // 0=Kh 1=Kl 2=Vf
            int i2 = idx & 511;
            int r = i2 >> 3, c = i2 & 7;
            const uint16_t* G =
                (mt == 0) ? (const uint16_t*)g_Kh :
                (mt == 1) ? (const uint16_t*)g_Kl : (const uint16_t*)g_Vf;
            CP16(base + mt * 8192 + sw_off(r, c),
                 G + ((size_t)bh * 2048 + kt * 64 + r) * 64 + c * 8);
        }
        CP_COMMIT();
    };

    // Q into smem (64 rows, hi+lo) — folded into group 0
#pragma unroll
    for (int j = 0; j < 4; j++) {
        int idx = j * 128 + tid;                 // 0..511
        int r = idx >> 3, c = idx & 7;
        CP16(sb + A_QH + sw_off(r, c), g_Qh + ((size_t)bh * 2048 + q0 + r) * 64 + c * 8);
        CP16(sb + A_QL + sw_off(r, c), g_Ql + ((size_t)bh * 2048 + q0 + r) * 64 + c * 8);
    }
    issueKV(0, 0);
    issueKV(1, 1);
    for (int i = tid; i < 4096; i += 128) biasS[i] = emb[g_lut[i] * 16 + h];

    float o[8][4];
#pragma unroll
    for (int i = 0; i < 8; i++)
#pragma unroll
        for (int j = 0; j < 4; j++) o[i][j] = 0.f;
    float m0r = -1e30f, m1r = -1e30f, L0 = 0.f, L1 = 0.f;

    const int qg = q0 + w * 16 + (lane >> 2);    // global q row (r0)
    const int mat = lane >> 3;
    const int rh = (mat & 1) * 8 + (lane & 7);

    for (int kt = 0; kt < 32; kt++) {
        if (kt == 31) { CP_WAIT(0); } else { CP_WAIT(1); }
        __syncthreads();
        if (kt + 2 < 32) issueKV(kt + 2, (kt + 2) % 3);
        uint32_t kvb = sb + A_STG + (kt % 3) * A_SSTR;

        // ----- S = Q K^T (split 3-mma, bf16) -----
        float sacc[8][4];
#pragma unroll
        for (int i = 0; i < 8; i++)
#pragma unroll
            for (int j = 0; j < 4; j++) sacc[i][j] = 0.f;

#pragma unroll
        for (int ks = 0; ks < 4; ks++) {
            int cc = (mat >> 1) + ks * 2;
            uint32_t aqh[4], aql[4];
            int qrow = w * 16 + rh;
            ldsm4(aqh, sb + A_QH + sw_off(qrow, cc));
            ldsm4(aql, sb + A_QL + sw_off(qrow, cc));
            uint32_t bkh[8][2], bkl[8][2];
#pragma unroll
            for (int p = 0; p < 4; p++) {
                int krow = p * 16 + rh;
                uint32_t t[4];
                ldsm4(t, kvb + A_KH + sw_off(krow, cc));
                bkh[2*p][0] = t[0]; bkh[2*p][1] = t[2];
                bkh[2*p+1][0] = t[1]; bkh[2*p+1][1] = t[3];
                ldsm4(t, kvb + A_KL + sw_off(krow, cc));
                bkl[2*p][0] = t[0]; bkl[2*p][1] = t[2];
                bkl[2*p+1][0] = t[1]; bkl[2*p+1][1] = t[3];
            }
#pragma unroll
            for (int nf = 0; nf < 8; nf++) {
                mma16816(sacc[nf], aqh, bkh[nf]);
                mma16816(sacc[nf], aqh, bkl[nf]);
                mma16816(sacc[nf], aql, bkh[nf]);
            }
        }

        // ----- softmax (rows r0 = qg, r1 = qg+8) -----
        int base0 = kt * 64 - qg + 2048;
        float mloc0 = m0r, mloc1 = m1r;
#pragma unroll
        for (int nf = 0; nf < 8; nf++) {
            int kb = nf * 8 + (lane & 3) * 2;
            sacc[nf][0] += biasS[base0 + kb];
            sacc[nf][1] += biasS[base0 + kb + 1];
            sacc[nf][2] += biasS[base0 - 8 + kb];
            sacc[nf][3] += biasS[base0 - 8 + kb + 1];
            mloc0 = fmaxf(mloc0, fmaxf(sacc[nf][0], sacc[nf][1]));
            mloc1 = fmaxf(mloc1, fmaxf(sacc[nf][2], sacc[nf][3]));
        }
        mloc0 = fmaxf(mloc0, __shfl_xor_sync(~0u, mloc0, 1));
        mloc0 = fmaxf(mloc0, __shfl_xor_sync(~0u, mloc0, 2));
        mloc1 = fmaxf(mloc1, __shfl_xor_sync(~0u, mloc1, 1));
        mloc1 = fmaxf(mloc1, __shfl_xor_sync(~0u, mloc1, 2));
        float corr0 = __expf(m0r - mloc0);
        float corr1 = __expf(m1r - mloc1);
        m0r = mloc0; m1r = mloc1;
        L0 *= corr0; L1 *= corr1;

        uint32_t aph[4][4];                     // P as fp16 (single precision term)
#pragma unroll
        for (int nf = 0; nf < 8; nf++) {
            float p0 = __expf(sacc[nf][0] - m0r);
            float p1 = __expf(sacc[nf][1] - m0r);
            float p2 = __expf(sacc[nf][2] - m1r);
            float p3 = __expf(sacc[nf][3] - m1r);
            L0 += p0 + p1; L1 += p2 + p3;
            int kc = nf >> 1, hf = nf & 1;
            aph[kc][hf ? 2 : 0] = packhf(p0, p1);
            aph[kc][hf ? 3 : 1] = packhf(p2, p3);
        }
#pragma unroll
        for (int nf = 0; nf < 8; nf++) {
            o[nf][0] *= corr0; o[nf][1] *= corr0;
            o[nf][2] *= corr1; o[nf][3] *= corr1;
        }

        // ----- O += P V (single fp16 term; V [key][dh] via ldmatrix.trans) -----
#pragma unroll
        for (int kc = 0; kc < 4; kc++) {
            uint32_t bvh[8][2];
#pragma unroll
            for (int p = 0; p < 4; p++) {
                int krow = kc * 16 + (mat & 1) * 8 + (lane & 7);
                int cc = p * 2 + (mat >> 1);
                uint32_t t[4];
                ldsm4t(t, kvb + A_VF + sw_off(krow, cc));
                bvh[2*p][0] = t[0]; bvh[2*p][1] = t[1];
                bvh[2*p+1][0] = t[2]; bvh[2*p+1][1] = t[3];
            }
#pragma unroll
            for (int nf = 0; nf < 8; nf++)
                mma16816h(o[nf], aph[kc], bvh[nf]);
        }
    }

    // ----- finalize -----
    L0 += __shfl_xor_sync(~0u, L0, 1);
    L0 += __shfl_xor_sync(~0u, L0, 2);
    L1 += __shfl_xor_sync(~0u, L1, 1);
    L1 += __shfl_xor_sync(~0u, L1, 2);
    float inv0 = 1.f / L0, inv1 = 1.f / L1;
    size_t ob0 = ((size_t)(b * 2048 + qg)) * 1024 + h * 64;
    size_t ob1 = ((size_t)(b * 2048 + qg + 8)) * 1024 + h * 64;
#pragma unroll
    for (int nf = 0; nf < 8; nf++) {
        int dh = nf * 8 + (lane & 3) * 2;
        float h0, l0v, h1, l1v;
        hilo(o[nf][0] * inv0, h0, l0v); hilo(o[nf][1] * inv0, h1, l1v);
        *(uint32_t*)(g_Oh + ob0 + dh) = packbf(h0, h1);
        *(uint32_t*)(g_Ol + ob0 + dh) = packbf(l0v, l1v);
        hilo(o[nf][2] * inv1, h0, l0v); hilo(o[nf][3] * inv1, h1, l1v);
        *(uint32_t*)(g_Oh + ob1 + dh) = packbf(h0, h1);
        *(uint32_t*)(g_Ol + ob1 + dh) = packbf(l0v, l1v);
    }
}

// ---------------- position_bias output: [16, 2048, 2048] ----------------
__global__ __launch_bounds__(256) void bias_out_kernel(const float* __restrict__ emb,
                                                       float* __restrict__ outb)
{
    int qq = blockIdx.x;
    int h  = blockIdx.y;
    float* rowp = outb + ((size_t)h * 2048 + qq) * 2048;
    int base = 2048 - qq;
#pragma unroll
    for (int half = 0; half < 2; half++) {
        int k = half * 1024 + threadIdx.x * 4;
        float4 r;
        r.x = emb[g_lut[base + k + 0] * 16 + h];
        r.y = emb[g_lut[base + k + 1] * 16 + h];
        r.z = emb[g_lut[base + k + 2] * 16 + h];
        r.w = emb[g_lut[base + k + 3] * 16 + h];
        *(float4*)(rowp + k) = r;
    }
}

// ---------------- launcher ----------------
extern "C" void kernel_launch(void* const* d_in, const int* in_sizes, int n_in,
                              void* d_out, int out_size)
{
    const float* H   = (const float*)d_in[0];
    const float* Wq  = (const float*)d_in[1];
    const float* Wk  = (const float*)d_in[2];
    const float* Wv  = (const float*)d_in[3];
    const float* Wo  = (const float*)d_in[4];
    const float* emb = (const float*)d_in[5];
    float* out = (float*)d_out;

    cudaFuncSetAttribute(mm_gemm, cudaFuncAttributeMaxDynamicSharedMemorySize, G_SMEM);
    cudaFuncSetAttribute(mm_attn, cudaFuncAttributeMaxDynamicSharedMemorySize, A_SMEM);

    lut_kernel<<<16, 256>>>();

    cvtH_kernel<<<1024, 256>>>(H, M_TOT * D_MODEL / 8);
    {
        dim3 grid(128, 4);
        cvtW_kernel<<<grid, 256>>>(Wq, Wk, Wv, Wo);
    }

    // QKV projections
    {
        dim3 grid(8, 64, 3);
        mm_gemm<<<grid, 256, G_SMEM>>>(0, nullptr);
    }
    // flash attention
    {
        dim3 grid(32, 64);
        mm_attn<<<grid, 128, A_SMEM>>>(emb);
    }
    // output projection
    {
        dim3 grid(8, 64, 1);
        mm_gemm<<<grid, 256, G_SMEM>>>(3, out);
    }
    // position_bias
    if (out_size >= ATTN_OUT_ELEMS + BIAS_OUT_ELEMS) {
        dim3 grid(2048, 16);
        bias_out_kernel<<<grid, 256>>>(emb, out + ATTN_OUT_ELEMS);
    }
}

// round 16
// speedup vs baseline: 1.6481x; 1.6481x over previous
#include <cuda_runtime.h>
#include <cuda_bf16.h>
#include <cuda_fp16.h>
#include <cstdint>

// ---------------- problem constants ----------------
#define D_MODEL   1024
#define S_LEN     2048
#define BATCH     4
#define N_HEADS   16
#define HEAD_DIM  64
#define BHX       (BATCH * N_HEADS)                          // 64
#define M_TOT     (BATCH * S_LEN)                            // 8192
#define ATTN_OUT_ELEMS  (BATCH * S_LEN * D_MODEL)            // 8388608
#define BIAS_OUT_ELEMS  (N_HEADS * S_LEN * S_LEN)            // 67108864

// ---------------- device scratch ----------------
__device__ __nv_bfloat16 g_Hh[(size_t)M_TOT * D_MODEL];
__device__ __nv_bfloat16 g_Hl[(size_t)M_TOT * D_MODEL];
__device__ __nv_bfloat16 g_Wh[4ull * D_MODEL * D_MODEL];
__device__ __nv_bfloat16 g_Wl[4ull * D_MODEL * D_MODEL];
__device__ __nv_bfloat16 g_Qh[(size_t)BHX * S_LEN * HEAD_DIM];
__device__ __nv_bfloat16 g_Ql[(size_t)BHX * S_LEN * HEAD_DIM];
__device__ __nv_bfloat16 g_Kh[(size_t)BHX * S_LEN * HEAD_DIM];
__device__ __nv_bfloat16 g_Kl[(size_t)BHX * S_LEN * HEAD_DIM];
__device__ __half        g_Vf[(size_t)BHX * S_LEN * HEAD_DIM];   // V single fp16
__device__ __nv_bfloat16 g_Oh[(size_t)M_TOT * D_MODEL];
__device__ __nv_bfloat16 g_Ol[(size_t)M_TOT * D_MODEL];
__device__ int g_lut[4096];

// ---------------- helpers ----------------
__device__ __forceinline__ uint32_t smem_u32(const void* p) {
    uint32_t a;
    asm("{ .reg .u64 t; cvta.to.shared.u64 t, %1; cvt.u32.u64 %0, t; }" : "=r"(a) : "l"(p));
    return a;
}
// row of 128B (8 x 16B chunks); XOR-swizzle chunk by row&7
__device__ __forceinline__ uint32_t sw_off(int row, int c) {
    return (uint32_t)(row * 128 + ((c ^ (row & 7)) << 4));
}
#define CP16(dst, src) asm volatile("cp.async.cg.shared.global [%0], [%1], 16;" :: "r"(dst), "l"(src))
#define CP_COMMIT()    asm volatile("cp.async.commit_group;" ::: "memory")
#define CP_WAIT(n)     asm volatile("cp.async.wait_group %0;" :: "n"(n) : "memory")

__device__ __forceinline__ void ldsm4(uint32_t r[4], uint32_t a) {
    asm volatile("ldmatrix.sync.aligned.m8n8.x4.shared.b16 {%0,%1,%2,%3}, [%4];"
                 : "=r"(r[0]), "=r"(r[1]), "=r"(r[2]), "=r"(r[3]) : "r"(a));
}
__device__ __forceinline__ void ldsm4t(uint32_t r[4], uint32_t a) {
    asm volatile("ldmatrix.sync.aligned.m8n8.x4.trans.shared.b16 {%0,%1,%2,%3}, [%4];"
                 : "=r"(r[0]), "=r"(r[1]), "=r"(r[2]), "=r"(r[3]) : "r"(a));
}
__device__ __forceinline__ void mma16816(float* c, const uint32_t* a, const uint32_t* b) {
    asm volatile("mma.sync.aligned.m16n8k16.row.col.f32.bf16.bf16.f32 "
                 "{%0,%1,%2,%3}, {%4,%5,%6,%7}, {%8,%9}, {%0,%1,%2,%3};"
                 : "+f"(c[0]), "+f"(c[1]), "+f"(c[2]), "+f"(c[3])
                 : "r"(a[0]), "r"(a[1]), "r"(a[2]), "r"(a[3]), "r"(b[0]), "r"(b[1]));
}
__device__ __forceinline__ void mma16816h(float* c, const uint32_t* a, const uint32_t* b) {
    asm volatile("mma.sync.aligned.m16n8k16.row.col.f32.f16.f16.f32 "
                 "{%0,%1,%2,%3}, {%4,%5,%6,%7}, {%8,%9}, {%0,%1,%2,%3};"
                 : "+f"(c[0]), "+f"(c[1]), "+f"(c[2]), "+f"(c[3])
                 : "r"(a[0]), "r"(a[1]), "r"(a[2]), "r"(a[3]), "r"(b[0]), "r"(b[1]));
}
__device__ __forceinline__ uint32_t packbf(float a, float b) {
    __nv_bfloat162 t = __floats2bfloat162_rn(a, b);
    return *(uint32_t*)&t;
}
__device__ __forceinline__ uint32_t packhf(float a, float b) {
    __half2 t = __floats2half2_rn(a, b);
    return *(uint32_t*)&t;
}
__device__ __forceinline__ void hilo(float x, float& h, float& l) {
    __nv_bfloat16 hb = __float2bfloat16(x);
    h = __bfloat162float(hb);
    l = x - h;
}

// ---------------- bucket LUT (exact integer math) ----------------
__global__ void lut_kernel() {
    int i = blockIdx.x * blockDim.x + threadIdx.x;
    if (i >= 4096) return;
    int d  = i - 2048;
    int rb = (d > 0) ? 16 : 0;
    int rp = (d < 0) ? -d : d;
    int b;
    if (rp < 8) b = rp;
    else {
        int n = (31 - __clz(rp * rp)) - 6;
        b = 8 + n;
        if (b > 15) b = 15;
    }
    g_lut[i] = rb + b;
}

// ---------------- fp32 -> bf16 hi/lo, 8 elements/thread ----------------
__device__ __forceinline__ void cvt_group8(const float4* s4, uint4* h4, uint4* l4, size_t g) {
    float4 a = s4[2 * g], b = s4[2 * g + 1];
    float x[8] = {a.x, a.y, a.z, a.w, b.x, b.y, b.z, b.w};
    float h[8], l[8];
#pragma unroll
    for (int t = 0; t < 8; t++) hilo(x[t], h[t], l[t]);
    h4[g] = make_uint4(packbf(h[0], h[1]), packbf(h[2], h[3]), packbf(h[4], h[5]), packbf(h[6], h[7]));
    l4[g] = make_uint4(packbf(l[0], l[1]), packbf(l[2], l[3]), packbf(l[4], l[5]), packbf(l[6], l[7]));
}

__global__ void cvtH_kernel(const float* __restrict__ src, int n8) {
    const float4* s4 = (const float4*)src;
    uint4* h4 = (uint4*)g_Hh;
    uint4* l4 = (uint4*)g_Hl;
    for (int g = blockIdx.x * blockDim.x + threadIdx.x; g < n8; g += gridDim.x * blockDim.x)
        cvt_group8(s4, h4, l4, g);
}

__global__ void cvtW_kernel(const float* __restrict__ w0, const float* __restrict__ w1,
                            const float* __restrict__ w2, const float* __restrict__ w3) {
    int z = blockIdx.y;
    const float* src = (z == 0) ? w0 : (z == 1) ? w1 : (z == 2) ? w2 : w3;
    const float4* s4 = (const float4*)src;
    uint4* h4 = (uint4*)(g_Wh + (size_t)z * D_MODEL * D_MODEL);
    uint4* l4 = (uint4*)(g_Wl + (size_t)z * D_MODEL * D_MODEL);
    const int n8 = D_MODEL * D_MODEL / 8;
    for (int g = blockIdx.x * blockDim.x + threadIdx.x; g < n8; g += gridDim.x * blockDim.x)
        cvt_group8(s4, h4, l4, g);
}

// ---------------- warp-MMA GEMM: C[8192,1024] = A * B^T ----------------
// tile 128x128, K-chunk 64, SINGLE-buffered (cross-CTA overlap, 2 CTAs/SM).
// smem: AH +0, AL +16384, BH +32768, BL +49152     (identical to R14 best)
#define G_SMEM 65536

__global__ __launch_bounds__(256, 2) void mm_gemm(int op, float* __restrict__ out) {
    extern __shared__ char sm[];
    uint32_t sb = smem_u32(sm);
    const int tid = threadIdx.x, lane = tid & 31, wid = tid >> 5;
    const int wm = wid & 1, wn = wid >> 1;       // 2 x 4 warps, warp tile 64m x 32n
    int mode = (op == 3) ? 3 : (int)blockIdx.z;
    const __nv_bfloat16* Ah = (op == 3) ? g_Oh : g_Hh;
    const __nv_bfloat16* Al = (op == 3) ? g_Ol : g_Hl;
    const __nv_bfloat16* Bh = g_Wh + (size_t)mode * D_MODEL * D_MODEL;
    const __nv_bfloat16* Bl = g_Wl + (size_t)mode * D_MODEL * D_MODEL;
    const int m0 = blockIdx.y * 128, n0 = blockIdx.x * 128;

    float acc[4][4][4];
#pragma unroll
    for (int i = 0; i < 4; i++)
#pragma unroll
        for (int j = 0; j < 4; j++)
#pragma unroll
            for (int k = 0; k < 4; k++) acc[i][j][k] = 0.f;

    for (int kc = 0; kc < 16; kc++) {
        if (kc) __syncthreads();                 // previous compute done before overwrite
        const __nv_bfloat16* mats[4] = {Ah, Al, Bh, Bl};
#pragma unroll
        for (int mt = 0; mt < 4; mt++) {
            const __nv_bfloat16* G = mats[mt];
            int rowbase = (mt < 2) ? m0 : n0;
#pragma unroll
            for (int j = 0; j < 4; j++) {
                int idx = j * 256 + tid;         // 0..1023
                int r = idx >> 3, c = idx & 7;
                CP16(sb + mt * 16384 + sw_off(r, c),
                     G + (size_t)(rowbase + r) * 1024 + kc * 64 + c * 8);
            }
        }
        CP_COMMIT();
        CP_WAIT(0);
        __syncthreads();
#pragma unroll
        for (int ks = 0; ks < 4; ks++) {
            uint32_t ah[4][4], al[4][4];
            int mat = lane >> 3;
            int rh = (mat & 1) * 8 + (lane & 7);
            int cc = (mat >> 1) + ks * 2;
#pragma unroll
            for (int mf = 0; mf < 4; mf++) {
                int row = wm * 64 + mf * 16 + rh;
                ldsm4(ah[mf], sb + sw_off(row, cc));
                ldsm4(al[mf], sb + 16384 + sw_off(row, cc));
            }
            uint32_t bh[4][2], bl[4][2];
#pragma unroll
            for (int p = 0; p < 2; p++) {
                int row = wn * 32 + p * 16 + rh;
                uint32_t t[4];
                ldsm4(t, sb + 32768 + sw_off(row, cc));
                bh[2*p][0] = t[0]; bh[2*p][1] = t[2];
                bh[2*p+1][0] = t[1]; bh[2*p+1][1] = t[3];
                ldsm4(t, sb + 49152 + sw_off(row, cc));
                bl[2*p][0] = t[0]; bl[2*p][1] = t[2];
                bl[2*p+1][0] = t[1]; bl[2*p+1][1] = t[3];
            }
#pragma unroll
            for (int mf = 0; mf < 4; mf++)
#pragma unroll
                for (int nf = 0; nf < 4; nf++) {
                    mma16816(acc[mf][nf], ah[mf], bh[nf]);
                    mma16816(acc[mf][nf], ah[mf], bl[nf]);
                    mma16816(acc[mf][nf], al[mf], bh[nf]);
                }
        }
    }

    // epilogue
#pragma unroll
    for (int mf = 0; mf < 4; mf++)
#pragma unroll
        for (int nf = 0; nf < 4; nf++) {
            int r0 = m0 + wm * 64 + mf * 16 + (lane >> 2);
            int col = n0 + wn * 32 + nf * 8 + (lane & 3) * 2;
            float* c = acc[mf][nf];
            if (mode == 3) {
                *(float2*)(out + (size_t)r0 * 1024 + col)       = make_float2(c[0], c[1]);
                *(float2*)(out + (size_t)(r0 + 8) * 1024 + col) = make_float2(c[2], c[3]);
            } else {
                int h = col >> 6, dh = col & 63;
#pragma unroll
                for (int rr = 0; rr < 2; rr++) {
                    int gi = r0 + rr * 8;
                    int b = gi >> 11, s = gi & 2047;
                    size_t o = ((size_t)(b * 16 + h) * 2048 + s) * 64 + dh;
                    if (mode == 2) {
                        *(uint32_t*)(g_Vf + o) = packhf(c[rr * 2], c[rr * 2 + 1]);
                    } else {
                        __nv_bfloat16* Dh = (mode == 0) ? g_Qh : g_Kh;
                        __nv_bfloat16* Dl = (mode == 0) ? g_Ql : g_Kl;
                        float h0, l0v, h1, l1v;
                        hilo(c[rr * 2], h0, l0v);
                        hilo(c[rr * 2 + 1], h1, l1v);
                        *(uint32_t*)(Dh + o) = packbf(h0, h1);
                        *(uint32_t*)(Dl + o) = packbf(l0v, l1v);
                    }
                }
            }
        }
}

// ---------------- warp-MMA flash attention ----------------
// CTA: 64 q rows x bh. 128 threads = 4 warps, warp = 16 q rows. 2 CTAs/SM.
// R14 double-buffered pipeline; V single fp16 (stage 24 KB).
// smem: QH 0 (8K), QL 8192 (8K); stages at 16384 (stride 24576):
//       KH+0 KL+8192 VF+16384; bias f32 @65536 (16K). total 81920.
#define A_QH    0
#define A_QL    8192
#define A_STG   16384
#define A_SSTR  24576
#define A_KH    0
#define A_KL    8192
#define A_VF    16384
#define A_BIAS  65536
#define A_SMEM  81920

__global__ __launch_bounds__(128, 2) void mm_attn(const float* __restrict__ emb) {
    extern __shared__ char sm[];
    uint32_t sb = smem_u32(sm);
    float* biasS = (float*)(sm + A_BIAS);
    const int tid = threadIdx.x, lane = tid & 31, w = tid >> 5;
    const int bh = blockIdx.y, h = bh & 15, b = bh >> 4;
    const int q0 = blockIdx.x * 64;

    // stage K/V loads for tile kt into buffer stg (Kh, Kl, Vf: 512 chunks each)
    auto issueKV = [&](int kt, int stg) {
        uint32_t base = sb + A_STG + stg * A_SSTR;
#pragma unroll
        for (int j = 0; j < 4; j++) {
            int idx = j * 128 + tid;             // 0..511
            int r = idx >> 3, c = idx & 7;
            size_t g = ((size_t)bh * 2048 + kt * 64 + r) * 64 + c * 8;
            CP16(base + A_KH + sw_off(r, c), (const uint16_t*)g_Kh + g);
            CP16(base + A_KL + sw_off(r, c), (const uint16_t*)g_Kl + g);
            CP16(base + A_VF + sw_off(r, c), (const uint16_t*)g_Vf + g);
        }
        CP_COMMIT();
    };

    // Q into smem (64 rows, hi+lo) — folded into group 0
#pragma unroll
    for (int j = 0; j < 4; j++) {
        int idx = j * 128 + tid;                 // 0..511
        int r = idx >> 3, c = idx & 7;
        CP16(sb + A_QH + sw_off(r, c), g_Qh + ((size_t)bh * 2048 + q0 + r) * 64 + c * 8);
        CP16(sb + A_QL + sw_off(r, c), g_Ql + ((size_t)bh * 2048 + q0 + r) * 64 + c * 8);
    }
    issueKV(0, 0);
    for (int i = tid; i < 4096; i += 128) biasS[i] = emb[g_lut[i] * 16 + h];

    float o[8][4];
#pragma unroll
    for (int i = 0; i < 8; i++)
#pragma unroll
        for (int j = 0; j < 4; j++) o[i][j] = 0.f;
    float m0r = -1e30f, m1r = -1e30f, L0 = 0.f, L1 = 0.f;

    const int qg = q0 + w * 16 + (lane >> 2);    // global q row (r0)
    const int mat = lane >> 3;
    const int rh = (mat & 1) * 8 + (lane & 7);

    for (int kt = 0; kt < 32; kt++) {
        int stg = kt & 1;
        if (kt + 1 < 32) { issueKV(kt + 1, stg ^ 1); CP_WAIT(1); }
        else             { CP_WAIT(0); }
        __syncthreads();
        uint32_t kvb = sb + A_STG + stg * A_SSTR;

        // ----- S = Q K^T (split 3-mma, bf16) -----
        float sacc[8][4];
#pragma unroll
        for (int i = 0; i < 8; i++)
#pragma unroll
            for (int j = 0; j < 4; j++) sacc[i][j] = 0.f;

#pragma unroll
        for (int ks = 0; ks < 4; ks++) {
            int cc = (mat >> 1) + ks * 2;
            uint32_t aqh[4], aql[4];
            int qrow = w * 16 + rh;
            ldsm4(aqh, sb + A_QH + sw_off(qrow, cc));
            ldsm4(aql, sb + A_QL + sw_off(qrow, cc));
            uint32_t bkh[8][2], bkl[8][2];
#pragma unroll
            for (int p = 0; p < 4; p++) {
                int krow = p * 16 + rh;
                uint32_t t[4];
                ldsm4(t, kvb + A_KH + sw_off(krow, cc));
                bkh[2*p][0] = t[0]; bkh[2*p][1] = t[2];
                bkh[2*p+1][0] = t[1]; bkh[2*p+1][1] = t[3];
                ldsm4(t, kvb + A_KL + sw_off(krow, cc));
                bkl[2*p][0] = t[0]; bkl[2*p][1] = t[2];
                bkl[2*p+1][0] = t[1]; bkl[2*p+1][1] = t[3];
            }
#pragma unroll
            for (int nf = 0; nf < 8; nf++) {
                mma16816(sacc[nf], aqh, bkh[nf]);
                mma16816(sacc[nf], aqh, bkl[nf]);
                mma16816(sacc[nf], aql, bkh[nf]);
            }
        }

        // ----- softmax (rows r0 = qg, r1 = qg+8) -----
        int base0 = kt * 64 - qg + 2048;
        float mloc0 = m0r, mloc1 = m1r;
#pragma unroll
        for (int nf = 0; nf < 8; nf++) {
            int kb = nf * 8 + (lane & 3) * 2;
            sacc[nf][0] += biasS[base0 + kb];
            sacc[nf][1] += biasS[base0 + kb + 1];
            sacc[nf][2] += biasS[base0 - 8 + kb];
            sacc[nf][3] += biasS[base0 - 8 + kb + 1];
            mloc0 = fmaxf(mloc0, fmaxf(sacc[nf][0], sacc[nf][1]));
            mloc1 = fmaxf(mloc1, fmaxf(sacc[nf][2], sacc[nf][3]));
        }
        mloc0 = fmaxf(mloc0, __shfl_xor_sync(~0u, mloc0, 1));
        mloc0 = fmaxf(mloc0, __shfl_xor_sync(~0u, mloc0, 2));
        mloc1 = fmaxf(mloc1, __shfl_xor_sync(~0u, mloc1, 1));
        mloc1 = fmaxf(mloc1, __shfl_xor_sync(~0u, mloc1, 2));
        float corr0 = __expf(m0r - mloc0);
        float corr1 = __expf(m1r - mloc1);
        m0r = mloc0; m1r = mloc1;
        L0 *= corr0; L1 *= corr1;

        uint32_t aph[4][4];                      // P as single fp16
#pragma unroll
        for (int nf = 0; nf < 8; nf++) {
            float p0 = __expf(sacc[nf][0] - m0r);
            float p1 = __expf(sacc[nf][1] - m0r);
            float p2 = __expf(sacc[nf][2] - m1r);
            float p3 = __expf(sacc[nf][3] - m1r);
            L0 += p0 + p1; L1 += p2 + p3;
            int kc = nf >> 1, hf = nf & 1;
            aph[kc][hf ? 2 : 0] = packhf(p0, p1);
            aph[kc][hf ? 3 : 1] = packhf(p2, p3);
        }
#pragma unroll
        for (int nf = 0; nf < 8; nf++) {
            o[nf][0] *= corr0; o[nf][1] *= corr0;
            o[nf][2] *= corr1; o[nf][3] *= corr1;
        }

        // ----- O += P V (single fp16 term; V [key][dh] via ldmatrix.trans) -----
#pragma unroll
        for (int kc = 0; kc < 4; kc++) {
            uint32_t bvh[8][2];
#pragma unroll
            for (int p = 0; p < 4; p++) {
                int krow = kc * 16 + (mat & 1) * 8 + (lane & 7);
                int cc = p * 2 + (mat >> 1);
                uint32_t t[4];
                ldsm4t(t, kvb + A_VF + sw_off(krow, cc));
                bvh[2*p][0] = t[0]; bvh[2*p][1] = t[1];
                bvh[2*p+1][0] = t[2]; bvh[2*p+1][1] = t[3];
            }
#pragma unroll
            for (int nf = 0; nf < 8; nf++)
                mma16816h(o[nf], aph[kc], bvh[nf]);
        }
        __syncthreads();
    }

    // ----- finalize -----
    L0 += __shfl_xor_sync(~0u, L0, 1);
    L0 += __shfl_xor_sync(~0u, L0, 2);
    L1 += __shfl_xor_sync(~0u, L1, 1);
    L1 += __shfl_xor_sync(~0u, L1, 2);
    float inv0 = 1.f / L0, inv1 = 1.f / L1;
    size_t ob0 = ((size_t)(b * 2048 + qg)) * 1024 + h * 64;
    size_t ob1 = ((size_t)(b * 2048 + qg + 8)) * 1024 + h * 64;
#pragma unroll
    for (int nf = 0; nf < 8; nf++) {
        int dh = nf * 8 + (lane & 3) * 2;
        float h0, l0v, h1, l1v;
        hilo(o[nf][0] * inv0, h0, l0v); hilo(o[nf][1] * inv0, h1, l1v);
        *(uint32_t*)(g_Oh + ob0 + dh) = packbf(h0, h1);
        *(uint32_t*)(g_Ol + ob0 + dh) = packbf(l0v, l1v);
        hilo(o[nf][2] * inv1, h0, l0v); hilo(o[nf][3] * inv1, h1, l1v);
        *(uint32_t*)(g_Oh + ob1 + dh) = packbf(h0, h1);
        *(uint32_t*)(g_Ol + ob1 + dh) = packbf(l0v, l1v);
    }
}

// ---------------- position_bias output: [16, 2048, 2048] ----------------
__global__ __launch_bounds__(256) void bias_out_kernel(const float* __restrict__ emb,
                                                       float* __restrict__ outb)
{
    int qq = blockIdx.x;
    int h  = blockIdx.y;
    float* rowp = outb + ((size_t)h * 2048 + qq) * 2048;
    int base = 2048 - qq;
#pragma unroll
    for (int half = 0; half < 2; half++) {
        int k = half * 1024 + threadIdx.x * 4;
        float4 r;
        r.x = emb[g_lut[base + k + 0] * 16 + h];
        r.y = emb[g_lut[base + k + 1] * 16 + h];
        r.z = emb[g_lut[base + k + 2] * 16 + h];
        r.w = emb[g_lut[base + k + 3] * 16 + h];
        *(float4*)(rowp + k) = r;
    }
}

// ---------------- launcher ----------------
extern "C" void kernel_launch(void* const* d_in, const int* in_sizes, int n_in,
                              void* d_out, int out_size)
{
    const float* H   = (const float*)d_in[0];
    const float* Wq  = (const float*)d_in[1];
    const float* Wk  = (const float*)d_in[2];
    const float* Wv  = (const float*)d_in[3];
    const float* Wo  = (const float*)d_in[4];
    const float* emb = (const float*)d_in[5];
    float* out = (float*)d_out;

    cudaFuncSetAttribute(mm_gemm, cudaFuncAttributeMaxDynamicSharedMemorySize, G_SMEM);
    cudaFuncSetAttribute(mm_attn, cudaFuncAttributeMaxDynamicSharedMemorySize, A_SMEM);

    lut_kernel<<<16, 256>>>();

    cvtH_kernel<<<1024, 256>>>(H, M_TOT * D_MODEL / 8);
    {
        dim3 grid(128, 4);
        cvtW_kernel<<<grid, 256>>>(Wq, Wk, Wv, Wo);
    }

    // QKV projections
    {
        dim3 grid(8, 64, 3);
        mm_gemm<<<grid, 256, G_SMEM>>>(0, nullptr);
    }
    // flash attention
    {
        dim3 grid(32, 64);
        mm_attn<<<grid, 128, A_SMEM>>>(emb);
    }
    // output projection
    {
        dim3 grid(8, 64, 1);
        mm_gemm<<<grid, 256, G_SMEM>>>(3, out);
    }
    // position_bias
    if (out_size >= ATTN_OUT_ELEMS + BIAS_OUT_ELEMS) {
        dim3 grid(2048, 16);
        bias_out_kernel<<<grid, 256>>>(emb, out + ATTN_OUT_ELEMS);
    }
}